// round 6
// baseline (speedup 1.0000x reference)
#include <cuda_runtime.h>

// QPSolver: N=32, M=64, BS=512, ITERS=1000, ALPHA=BETA=1
// Out layout (float32): Xs (512,1001,128) then primal_sols (512,1001,32).

#define BSZ   512
#define NDIM  32
#define MDIM  64
#define ITERS 1000

typedef unsigned long long ull;

__device__ __align__(16) float gD[MDIM * MDIM];      // D = H P^-1 H^T
__device__ __align__(16) float gHinv[NDIM * MDIM];   // pinv(H) (32x64)
__device__ __align__(16) float gWq[NDIM * MDIM];     // P^-1 H^T (32x64)
__device__ float gC;                                 // 1/lambda_max(D)

__device__ __forceinline__ float pairsum2(ull a, ull b) {
    ull s; asm("add.rn.f32x2 %0,%1,%2;" : "=l"(s) : "l"(a), "l"(b));
    unsigned lo, hi;
    asm("mov.b64 {%0,%1},%2;" : "=r"(lo), "=r"(hi) : "l"(s));
    return __uint_as_float(lo) + __uint_as_float(hi);
}
__device__ __forceinline__ ull dup2(float a) {
    ull r; asm("mov.b64 %0,{%1,%1};" : "=l"(r) : "f"(a)); return r;
}

// ---------------------------------------------------------------------------
// Gauss-Jordan, 32 x 96 augmented (pitch 97), 512 threads, 3 syncs per pivot.
// ---------------------------------------------------------------------------
__device__ void gj97(float* A, float* fraw, float* fvec, int* spiv, float* sinv) {
    int t = threadIdx.x;
    for (int col = 0; col < 32; col++) {
        // Phase A: warp0 argmax pivot + inv; warp1 snapshots column col.
        if (t < 32) {
            float v = (t >= col) ? fabsf(A[t * 97 + col]) : -1.0f;
            int idx = t;
            for (int o = 16; o; o >>= 1) {
                float v2 = __shfl_down_sync(0xffffffffu, v, o);
                int i2 = __shfl_down_sync(0xffffffffu, idx, o);
                if (v2 > v) { v = v2; idx = i2; }
            }
            if (t == 0) { *spiv = idx; *sinv = 1.0f / A[idx * 97 + col]; }
        } else if (t < 64) {
            fraw[t - 32] = A[(t - 32) * 97 + col];
        }
        __syncthreads();
        int piv = *spiv; float inv = *sinv;
        // Phase B: swap + scale pivot row; build fvec from snapshot.
        if (t < 96) {
            float tmp = A[piv * 97 + t];
            A[piv * 97 + t] = A[col * 97 + t];
            A[col * 97 + t] = tmp * inv;
        } else if (t >= 128 && t < 160) {
            int r = t - 128;
            fvec[r] = (r == col) ? 0.0f : ((r == piv) ? fraw[col] : fraw[r]);
        }
        __syncthreads();
        // Phase C: eliminate. r = lane (conflict-free with pitch 97).
        {
            int r = t & 31;
            float f = fvec[r];
            if (r != col) {
                for (int j = (t >> 5); j < 96; j += 16)
                    A[r * 97 + j] = fmaf(-f, A[col * 97 + j], A[r * 97 + j]);
            }
        }
        __syncthreads();
    }
}

// ---------------------------------------------------------------------------
// Setup: Wq = P^-1 H^T, D = H Wq, Hinv = (H^T H)^-1 H^T, c = 1/lambda_max(D)
// ---------------------------------------------------------------------------
__global__ void setup_kernel(const float* __restrict__ P, const float* __restrict__ H) {
    __shared__ __align__(16) float sm[11296];
    float* sH   = sm;            // 2048
    float* sA   = sm + 2048;     // 3104 (32x97)
    float* sWq  = sm + 5152;     // 2048
    float* sD   = sm + 7200;     // 4096
    float* sTmp = sm;            // 4096 (aliases sH+sA, both dead by then)
    __shared__ float fraw[32], fvec[32], sV[64], sW[64];
    __shared__ float sinvS, sNrm;
    __shared__ int spivS;
    __shared__ double sT[8];

    int t = threadIdx.x;

    for (int i = t; i < 2048; i += 512) sH[i] = H[i];
    __syncthreads();

    // aug1 = [P | H^T]
    {
        int r = t & 31;
        for (int j = (t >> 5); j < 96; j += 16)
            sA[r * 97 + j] = (j < 32) ? P[r * 32 + j] : sH[(j - 32) * 32 + r];
    }
    __syncthreads();
    gj97(sA, fraw, fvec, &spivS, &sinvS);
    for (int i = t; i < 2048; i += 512) {
        float v = sA[(i >> 6) * 97 + 32 + (i & 63)];
        sWq[i] = v; gWq[i] = v;
    }
    __syncthreads();

    // D = H * Wq (64x64), packed f32x2
    {
        int r = t >> 3, cb = (t & 7) * 4;
        ull acc[4] = {0ull, 0ull, 0ull, 0ull};
        for (int k = 0; k < 32; k++) {
            ull ap = dup2(sH[r * 32 + k]);
            const ull* row = (const ull*)(sWq + k * 64);
#pragma unroll
            for (int j = 0; j < 4; j++)
                asm("fma.rn.f32x2 %0,%1,%2,%0;" : "+l"(acc[j]) : "l"(ap), "l"(row[cb + j]));
        }
        ull* drow = (ull*)(sD + r * 64);
        ull* grow = (ull*)(gD + r * 64);
#pragma unroll
        for (int j = 0; j < 4; j++) { drow[cb + j] = acc[j]; grow[cb + j] = acc[j]; }
    }
    __syncthreads();

    // aug2 = [H^T H | H^T]
    {
        int r = t >> 4, c0 = (t & 15) * 2;
        float s0 = 0.0f, s1 = 0.0f;
        for (int k = 0; k < 64; k++) {
            float a = sH[k * 32 + r];
            s0 = fmaf(a, sH[k * 32 + c0], s0);
            s1 = fmaf(a, sH[k * 32 + c0 + 1], s1);
        }
        sA[r * 97 + c0] = s0; sA[r * 97 + c0 + 1] = s1;
        for (int j = (t & 15); j < 64; j += 16) sA[r * 97 + 32 + j] = sH[j * 32 + r];
    }
    __syncthreads();
    gj97(sA, fraw, fvec, &spivS, &sinvS);
    for (int i = t; i < 2048; i += 512) gHinv[i] = sA[(i >> 6) * 97 + 32 + (i & 63)];
    __syncthreads();

    // trace-normalize D, 5 squarings
    if (t < 32) {
        float v = sD[t * 65] + sD[(t + 32) * 65];
        for (int o = 16; o; o >>= 1) v += __shfl_xor_sync(0xffffffffu, v, o);
        if (t == 0) sT[0] = (double)v;
    }
    __syncthreads();
    {
        float inv = (float)(1.0 / sT[0]);
        for (int i = t; i < 4096; i += 512) sD[i] *= inv;
    }
    __syncthreads();
    for (int s = 1; s <= 5; s++) {
        {
            int r = t >> 3, cb = (t & 7) * 4;
            ull acc[4] = {0ull, 0ull, 0ull, 0ull};
            for (int k = 0; k < 64; k++) {
                ull ap = dup2(sD[r * 64 + k]);
                const ull* row = (const ull*)(sD + k * 64);
#pragma unroll
                for (int j = 0; j < 4; j++)
                    asm("fma.rn.f32x2 %0,%1,%2,%0;" : "+l"(acc[j]) : "l"(ap), "l"(row[cb + j]));
            }
            ull* trow = (ull*)(sTmp + r * 64);
#pragma unroll
            for (int j = 0; j < 4; j++) trow[cb + j] = acc[j];
        }
        __syncthreads();
        if (t < 32) {
            float v = sTmp[t * 65] + sTmp[(t + 32) * 65];
            for (int o = 16; o; o >>= 1) v += __shfl_xor_sync(0xffffffffu, v, o);
            if (t == 0) sT[s] = (double)v;
        }
        __syncthreads();
        {
            float inv = (float)(1.0 / sT[s]);
            for (int i = t; i < 4096; i += 512) sD[i] = sTmp[i] * inv;
        }
        __syncthreads();
    }

    // 16 power iterations on D^32 (8-lane groups per row)
    if (t < 64) sV[t] = 1.0f + 0.001f * (float)t;
    __syncthreads();
    for (int it = 0; it < 16; it++) {
        int r = t >> 3, j = t & 7;
        float p = 0.0f;
#pragma unroll
        for (int kk = 0; kk < 8; kk++)
            p = fmaf(sD[r * 64 + j * 8 + kk], sV[j * 8 + kk], p);
        p += __shfl_xor_sync(0xffffffffu, p, 1);
        p += __shfl_xor_sync(0xffffffffu, p, 2);
        p += __shfl_xor_sync(0xffffffffu, p, 4);
        if (j == 0) sW[r] = p;
        __syncthreads();
        if (t < 32) {
            float v = fmaxf(fabsf(sW[t]), fabsf(sW[t + 32]));
            for (int o = 16; o; o >>= 1) v = fmaxf(v, __shfl_xor_sync(0xffffffffu, v, o));
            if (t == 0) sNrm = 1.0f / v;
        }
        __syncthreads();
        if (t < 64) sV[t] = sW[t] * sNrm;
        __syncthreads();
    }
    // final matvec for Rayleigh
    {
        int r = t >> 3, j = t & 7;
        float p = 0.0f;
#pragma unroll
        for (int kk = 0; kk < 8; kk++)
            p = fmaf(sD[r * 64 + j * 8 + kk], sV[j * 8 + kk], p);
        p += __shfl_xor_sync(0xffffffffu, p, 1);
        p += __shfl_xor_sync(0xffffffffu, p, 2);
        p += __shfl_xor_sync(0xffffffffu, p, 4);
        if (j == 0) sW[r] = p;
    }
    __syncthreads();
    if (t == 0) {
        double num = 0.0, den = 0.0;
        for (int i = 0; i < 64; i++) {
            num += (double)sV[i] * (double)sW[i];
            den += (double)sV[i] * (double)sV[i];
        }
        double lam = num / den;
        for (int s = 5; s >= 1; s--) lam = sqrt(sT[s] * lam);
        gC = (float)(1.0 / (sT[0] * lam));
    }
}

// ---------------------------------------------------------------------------
// Main solver: warp-per-row. Hot loop = 16 LDS.128 + 64 FFMA2 + 4 STG only.
// y' = c*(D y + z) + mu ;  z' = relu(y + z - 2 y')
// ---------------------------------------------------------------------------
__global__ void __launch_bounds__(128, 1) solve_kernel(
    const float* __restrict__ q, const float* __restrict__ b, float* __restrict__ out)
{
    __shared__ __align__(16) float sy[4][64];
    int tid = threadIdx.x, lane = tid & 31, wid = tid >> 5;
    int row = blockIdx.x * 4 + wid;
    float c = gC;

    ull dA2[32], dB2[32];
    const ull* gD2 = (const ull*)gD;
#pragma unroll
    for (int i = 0; i < 32; i++) {
        dA2[i] = gD2[lane * 32 + i];
        dB2[i] = gD2[(lane + 32) * 32 + i];
    }

    const float* qr = q + row * NDIM;
    const float* br = b + (size_t)row * MDIM;
    float mu0 = 0.0f, mu1 = 0.0f;
#pragma unroll
    for (int i = 0; i < 32; i++) {
        float qi = qr[i];
        mu0 = fmaf(qi, gWq[i * 64 + lane], mu0);
        mu1 = fmaf(qi, gWq[i * 64 + lane + 32], mu1);
    }
    mu0 = c * (mu0 - br[lane]);
    mu1 = c * (mu1 - br[lane + 32]);

    float* Xp = out + (size_t)row * (ITERS + 1) * 128;
    Xp[lane] = 0.0f; Xp[lane + 32] = 0.0f; Xp[lane + 64] = 0.0f; Xp[lane + 96] = 0.0f;

    unsigned syb = (unsigned)__cvta_generic_to_shared(&sy[wid][0]);
    asm volatile("st.shared.f32 [%0], %1;" :: "r"(syb + 4u * lane), "f"(0.0f));
    asm volatile("st.shared.f32 [%0], %1;" :: "r"(syb + 4u * (lane + 32)), "f"(0.0f));
    __syncwarp();

    float y0 = 0.0f, y1 = 0.0f, z0 = 0.0f, z1 = 0.0f;
    bool conv = false;
    float* xk = Xp + 128;

    for (int k = 1; k <= ITERS; k++) {
        if (!conv) {
            ull a0 = 0ull, a1 = 0ull, c0 = 0ull, c1 = 0ull;
#pragma unroll
            for (int tq = 0; tq < 16; tq++) {
                ull yp0, yp1;
                asm volatile("ld.shared.v2.b64 {%0,%1},[%2];"
                             : "=l"(yp0), "=l"(yp1) : "r"(syb + 16u * tq));
                asm("fma.rn.f32x2 %0,%1,%2,%0;" : "+l"(a0) : "l"(dA2[2 * tq]),     "l"(yp0));
                asm("fma.rn.f32x2 %0,%1,%2,%0;" : "+l"(a1) : "l"(dA2[2 * tq + 1]), "l"(yp1));
                asm("fma.rn.f32x2 %0,%1,%2,%0;" : "+l"(c0) : "l"(dB2[2 * tq]),     "l"(yp0));
                asm("fma.rn.f32x2 %0,%1,%2,%0;" : "+l"(c1) : "l"(dB2[2 * tq + 1]), "l"(yp1));
            }
            float w0 = pairsum2(a0, a1);
            float w1 = pairsum2(c0, c1);

            float ny0 = fmaf(c, w0 + z0, mu0);
            float ny1 = fmaf(c, w1 + z1, mu1);
            float nz0 = fmaxf(fmaf(-2.0f, ny0, y0 + z0), 0.0f);
            float nz1 = fmaxf(fmaf(-2.0f, ny1, y1 + z1), 0.0f);

            bool same = (ny0 == y0) && (ny1 == y1) && (nz0 == z0) && (nz1 == z1);
            unsigned bl = __ballot_sync(0xffffffffu, same);

            y0 = ny0; y1 = ny1; z0 = nz0; z1 = nz1;

            if (bl == 0xffffffffu) {
                conv = true;   // exact fp32 fixed point: future iterates identical
            } else {
                asm volatile("st.shared.f32 [%0], %1;" :: "r"(syb + 4u * lane),        "f"(y0));
                asm volatile("st.shared.f32 [%0], %1;" :: "r"(syb + 4u * (lane + 32)), "f"(y1));
                __syncwarp();
            }
        }
        xk[lane] = y0; xk[lane + 32] = y1; xk[lane + 64] = z0; xk[lane + 96] = z1;
        xk += 128;
    }
}

// ---------------------------------------------------------------------------
// Primal postprocess: p[b,k,n] = Hinv[n,:] . Xs[b,k,64:128] - Hinv[n,:] . b[b,:]
// 512 blocks x 8 warps; warp w of block b handles k = w, w+8, ...
// ---------------------------------------------------------------------------
__global__ void __launch_bounds__(256) primal_kernel(
    const float* __restrict__ b, float* __restrict__ out)
{
    int lane = threadIdx.x & 31, w = threadIdx.x >> 5;
    int row = blockIdx.x;

    ull hv[32];
    const ull* g2 = (const ull*)gHinv;
#pragma unroll
    for (int i = 0; i < 32; i++) hv[i] = g2[lane * 32 + i];

    // hb = Hinv[lane] . b_row
    const ulonglong2* b2 = (const ulonglong2*)(b + (size_t)row * MDIM);
    ull h0 = 0ull, h1 = 0ull;
#pragma unroll
    for (int i = 0; i < 16; i++) {
        ulonglong2 v = b2[i];
        asm("fma.rn.f32x2 %0,%1,%2,%0;" : "+l"(h0) : "l"(hv[2 * i]),     "l"(v.x));
        asm("fma.rn.f32x2 %0,%1,%2,%0;" : "+l"(h1) : "l"(hv[2 * i + 1]), "l"(v.y));
    }
    float hb = pairsum2(h0, h1);

    const float* Xbase = out + (size_t)row * (ITERS + 1) * 128;
    float* Pp = out + (size_t)BSZ * (ITERS + 1) * 128 + (size_t)row * (ITERS + 1) * 32;

    for (int k = w; k <= ITERS; k += 8) {
        const ulonglong2* z2 = (const ulonglong2*)(Xbase + (size_t)k * 128 + 64);
        ull p0 = 0ull, p1 = 0ull;
#pragma unroll
        for (int i = 0; i < 16; i++) {
            ulonglong2 v = z2[i];
            asm("fma.rn.f32x2 %0,%1,%2,%0;" : "+l"(p0) : "l"(hv[2 * i]),     "l"(v.x));
            asm("fma.rn.f32x2 %0,%1,%2,%0;" : "+l"(p1) : "l"(hv[2 * i + 1]), "l"(v.y));
        }
        Pp[k * 32 + lane] = pairsum2(p0, p1) - hb;
    }
}

extern "C" void kernel_launch(void* const* d_in, const int* in_sizes, int n_in,
                              void* d_out, int out_size) {
    const float *q = nullptr, *b = nullptr, *P = nullptr, *H = nullptr;
    for (int i = 0; i < n_in; i++) {
        switch (in_sizes[i]) {
            case BSZ * NDIM:  q = (const float*)d_in[i]; break;  // 16384
            case BSZ * MDIM:  b = (const float*)d_in[i]; break;  // 32768
            case NDIM * NDIM: P = (const float*)d_in[i]; break;  // 1024
            case MDIM * NDIM: H = (const float*)d_in[i]; break;  // 2048
            default: break;                                      // iters ignored
        }
    }
    setup_kernel<<<1, 512>>>(P, H);
    solve_kernel<<<BSZ / 4, 128>>>(q, b, (float*)d_out);
    primal_kernel<<<BSZ, 256>>>(b, (float*)d_out);
}

// round 7
// speedup vs baseline: 1.6971x; 1.6971x over previous
#include <cuda_runtime.h>

// QPSolver: N=32, M=64, BS=512, ITERS=1000, ALPHA=BETA=1
// Out layout (float32): Xs (512,1001,128) then primal_sols (512,1001,32).

#define BSZ   512
#define NDIM  32
#define MDIM  64
#define ITERS 1000

typedef unsigned long long ull;

__device__ __align__(16) float gD[MDIM * MDIM];      // D = H P^-1 H^T
__device__ __align__(16) float gHinv[NDIM * MDIM];   // pinv(H) (32x64)
__device__ __align__(16) float gWq[NDIM * MDIM];     // P^-1 H^T (32x64)
__device__ float gC;                                 // 1/lambda_max(D)

#define FMA2(acc, x, y) asm("fma.rn.f32x2 %0,%1,%2,%0;" : "+l"(acc) : "l"(x), "l"(y))

__device__ __forceinline__ float pairsum2(ull a, ull b) {
    ull s; asm("add.rn.f32x2 %0,%1,%2;" : "=l"(s) : "l"(a), "l"(b));
    unsigned lo, hi;
    asm("mov.b64 {%0,%1},%2;" : "=r"(lo), "=r"(hi) : "l"(s));
    return __uint_as_float(lo) + __uint_as_float(hi);
}
__device__ __forceinline__ float red4(ull a0, ull a1, ull a2, ull a3) {
    ull s0, s1, s;
    asm("add.rn.f32x2 %0,%1,%2;" : "=l"(s0) : "l"(a0), "l"(a1));
    asm("add.rn.f32x2 %0,%1,%2;" : "=l"(s1) : "l"(a2), "l"(a3));
    asm("add.rn.f32x2 %0,%1,%2;" : "=l"(s)  : "l"(s0), "l"(s1));
    unsigned lo, hi;
    asm("mov.b64 {%0,%1},%2;" : "=r"(lo), "=r"(hi) : "l"(s));
    return __uint_as_float(lo) + __uint_as_float(hi);
}
__device__ __forceinline__ ull dup2(float a) {
    ull r; asm("mov.b64 %0,{%1,%1};" : "=l"(r) : "f"(a)); return r;
}

// ---------------------------------------------------------------------------
// Warp-scope Gauss-Jordan on a 32 x 96 system, rows in registers, shfl
// broadcast, NO barriers, NO pivoting (SPD left block). Lane l holds row l.
// On return a[32..95] holds the solution row l.
// ---------------------------------------------------------------------------
__device__ __forceinline__ void gj_warp(float a[96], int lane) {
    for (int c = 0; c < 32; c++) {
        float myc = 0.0f;
#pragma unroll
        for (int j = 0; j < 32; j++) if (j == c) myc = a[j];   // SEL scan
        float pv = __shfl_sync(0xffffffffu, myc, c);
        float inv = 1.0f / pv;
        float f = myc * inv;
        bool isp = (lane == c);
#pragma unroll
        for (int j = 0; j < 96; j++) {
            float pr = __shfl_sync(0xffffffffu, a[j], c);
            a[j] = isp ? pr * inv : fmaf(-f, pr, a[j]);
        }
    }
}

// ---------------------------------------------------------------------------
// Setup (1 block, 256 threads): Wq = P^-1 H^T, Hinv = (H^T H)^-1 H^T (two
// concurrent zero-barrier warp GJs), D = H Wq, c = 1/lambda_max(D) via 5
// trace-normalized squarings + warp-scope power iteration.
// ---------------------------------------------------------------------------
__global__ void __launch_bounds__(256) setup_kernel(
    const float* __restrict__ P, const float* __restrict__ H)
{
    __shared__ __align__(16) float sm[8192];
    float* sH   = sm;          // 2048 (H, 64x32)
    float* sWq  = sm + 2048;   // 2048
    float* sD   = sm + 4096;   // 4096
    float* sTmp = sm;          // 4096 (aliases sH+sWq; both dead by squaring)
    __shared__ float sV[64];
    __shared__ double sT[8];

    int t = threadIdx.x, lane = t & 31, w = t >> 5;

    for (int i = t; i < 2048; i += 256) sH[i] = H[i];
    __syncthreads();

    if (w == 0) {
        // solve P * Wq = H^T
        float a[96];
#pragma unroll
        for (int j = 0; j < 32; j++) a[j] = P[lane * 32 + j];
#pragma unroll
        for (int j = 0; j < 64; j++) a[32 + j] = sH[j * 32 + lane];
        gj_warp(a, lane);
#pragma unroll
        for (int j = 0; j < 64; j++) {
            sWq[lane * 64 + j] = a[32 + j];
            gWq[lane * 64 + j] = a[32 + j];
        }
    } else if (w == 1) {
        // G = H^T H (row lane), then solve G * Hinv = H^T
        ull acc[16];
#pragma unroll
        for (int j = 0; j < 16; j++) acc[j] = 0ull;
        for (int kk = 0; kk < 64; kk++) {
            ull hl = dup2(sH[kk * 32 + lane]);
            const ull* hr = (const ull*)(sH + kk * 32);
#pragma unroll
            for (int j = 0; j < 16; j++) FMA2(acc[j], hl, hr[j]);
        }
        float a[96];
#pragma unroll
        for (int j = 0; j < 16; j++) {
            unsigned lo, hi;
            asm("mov.b64 {%0,%1},%2;" : "=r"(lo), "=r"(hi) : "l"(acc[j]));
            a[2 * j] = __uint_as_float(lo);
            a[2 * j + 1] = __uint_as_float(hi);
        }
#pragma unroll
        for (int j = 0; j < 64; j++) a[32 + j] = sH[j * 32 + lane];
        gj_warp(a, lane);
#pragma unroll
        for (int j = 0; j < 64; j++) gHinv[lane * 64 + j] = a[32 + j];
    }
    __syncthreads();

    // D = H * Wq (64x64): 256 threads, 16 outputs each
    {
        int r = t >> 2, cb = (t & 3) * 8;
        ull acc[8];
#pragma unroll
        for (int j = 0; j < 8; j++) acc[j] = 0ull;
        for (int kk = 0; kk < 32; kk++) {
            ull ap = dup2(sH[r * 32 + kk]);
            const ull* rw = (const ull*)(sWq + kk * 64);
#pragma unroll
            for (int j = 0; j < 8; j++) FMA2(acc[j], ap, rw[cb + j]);
        }
        ull* drow = (ull*)(sD + r * 64);
        ull* grow = (ull*)(gD + r * 64);
#pragma unroll
        for (int j = 0; j < 8; j++) { drow[cb + j] = acc[j]; grow[cb + j] = acc[j]; }
    }
    __syncthreads();

    // trace normalize + 5 squarings
    if (t < 32) {
        float v = sD[t * 65] + sD[(t + 32) * 65];
        for (int o = 16; o; o >>= 1) v += __shfl_xor_sync(0xffffffffu, v, o);
        if (t == 0) sT[0] = (double)v;
    }
    __syncthreads();
    {
        float inv = (float)(1.0 / sT[0]);
        for (int i = t; i < 4096; i += 256) sD[i] *= inv;
    }
    __syncthreads();
    for (int s = 1; s <= 5; s++) {
        {
            int r = t >> 2, cb = (t & 3) * 8;
            ull acc[8];
#pragma unroll
            for (int j = 0; j < 8; j++) acc[j] = 0ull;
            for (int kk = 0; kk < 64; kk++) {
                ull ap = dup2(sD[r * 64 + kk]);
                const ull* rw = (const ull*)(sD + kk * 64);
#pragma unroll
                for (int j = 0; j < 8; j++) FMA2(acc[j], ap, rw[cb + j]);
            }
            ull* trow = (ull*)(sTmp + r * 64);
#pragma unroll
            for (int j = 0; j < 8; j++) trow[cb + j] = acc[j];
        }
        __syncthreads();
        if (t < 32) {
            float v = sTmp[t * 65] + sTmp[(t + 32) * 65];
            for (int o = 16; o; o >>= 1) v += __shfl_xor_sync(0xffffffffu, v, o);
            if (t == 0) sT[s] = (double)v;
        }
        __syncthreads();
        {
            float inv = (float)(1.0 / sT[s]);
            for (int i = t; i < 4096; i += 256) sD[i] = sTmp[i] * inv;
        }
        __syncthreads();
    }

    // warp-scope power iteration: D^32 rows (lane, lane+32) in registers
    if (w == 0) {
        ull d0[32], d1[32];
        const ull* sD2 = (const ull*)sD;
#pragma unroll
        for (int i = 0; i < 32; i++) {
            d0[i] = sD2[lane * 32 + i];
            d1[i] = sD2[(lane + 32) * 32 + i];
        }
        sV[lane] = 1.0f + 0.001f * (float)lane;
        sV[lane + 32] = 1.0f + 0.001f * (float)(lane + 32);
        __syncwarp();
        float v0 = sV[lane], v1 = sV[lane + 32], w0 = 0.0f, w1 = 0.0f;
        for (int it = 0; it <= 16; it++) {
            ull a0 = 0ull, a1 = 0ull, b0 = 0ull, b1 = 0ull;
            const ull* vv = (const ull*)sV;
#pragma unroll
            for (int i = 0; i < 32; i++) {
                ull vp = vv[i];
                if (i & 1) { FMA2(a1, d0[i], vp); FMA2(b1, d1[i], vp); }
                else       { FMA2(a0, d0[i], vp); FMA2(b0, d1[i], vp); }
            }
            w0 = pairsum2(a0, a1);
            w1 = pairsum2(b0, b1);
            if (it == 16) break;
            float m = fmaxf(fabsf(w0), fabsf(w1));
            for (int o = 16; o; o >>= 1) m = fmaxf(m, __shfl_xor_sync(0xffffffffu, m, o));
            float inv = 1.0f / m;
            v0 = w0 * inv; v1 = w1 * inv;
            sV[lane] = v0; sV[lane + 32] = v1;
            __syncwarp();
        }
        float num = v0 * w0 + v1 * w1;
        float den = v0 * v0 + v1 * v1;
        for (int o = 16; o; o >>= 1) {
            num += __shfl_xor_sync(0xffffffffu, num, o);
            den += __shfl_xor_sync(0xffffffffu, den, o);
        }
        if (lane == 0) {
            double lam = (double)num / (double)den;
            for (int s = 5; s >= 1; s--) lam = sqrt(sT[s] * lam);
            gC = (float)(1.0 / (sT[0] * lam));
        }
    }
}

// ---------------------------------------------------------------------------
// Solver: 2 warps per row (block=64, grid=512). Lane owns output r = lane+32w.
// y' = c*(D y + z) + mu ;  z' = relu(y + z - 2 y'). Double-buffered y in smem.
// ---------------------------------------------------------------------------
__global__ void __launch_bounds__(64) solve_kernel(
    const float* __restrict__ q, const float* __restrict__ b, float* __restrict__ out)
{
    __shared__ __align__(16) float sy[2][64];
    int lane = threadIdx.x & 31, w = threadIdx.x >> 5;
    int r = lane + 32 * w;
    int row = blockIdx.x;
    float c = gC;

    // D row r resident: 32 ull = 64 floats
    ull dR[32];
    const ull* gD2 = (const ull*)gD;
#pragma unroll
    for (int i = 0; i < 32; i++) dR[i] = gD2[r * 32 + i];

    const float* qr = q + row * NDIM;
    const float* br = b + (size_t)row * MDIM;
    float mu = 0.0f;
#pragma unroll
    for (int i = 0; i < 32; i++) mu = fmaf(qr[i], gWq[i * 64 + r], mu);
    mu = c * (mu - br[r]);

    float* Xp = out + (size_t)row * (ITERS + 1) * 128;
    Xp[r] = 0.0f; Xp[64 + r] = 0.0f;           // k = 0
    sy[0][r] = 0.0f;
    __syncthreads();

    unsigned sb = (unsigned)__cvta_generic_to_shared(&sy[0][0]);
    float y = 0.0f, z = 0.0f;
    float* xk = Xp + 128;

    for (int k = 1; k <= ITERS; k++) {
        unsigned rb = sb + (((k & 1) ^ 1) << 8);   // read buf (k-1)&1
        unsigned wb = sb + ((k & 1) << 8);         // write buf k&1
        ull a0 = 0ull, a1 = 0ull, a2 = 0ull, a3 = 0ull;
#pragma unroll
        for (int i = 0; i < 8; i++) {
            ull p0, p1, p2, p3;
            asm volatile("ld.shared.v2.b64 {%0,%1},[%2];"
                         : "=l"(p0), "=l"(p1) : "r"(rb + 32u * i));
            asm volatile("ld.shared.v2.b64 {%0,%1},[%2];"
                         : "=l"(p2), "=l"(p3) : "r"(rb + 32u * i + 16u));
            FMA2(a0, dR[4 * i + 0], p0);
            FMA2(a1, dR[4 * i + 1], p1);
            FMA2(a2, dR[4 * i + 2], p2);
            FMA2(a3, dR[4 * i + 3], p3);
        }
        float wsum = red4(a0, a1, a2, a3);
        float ny = fmaf(c, wsum + z, mu);
        float nz = fmaxf(fmaf(-2.0f, ny, y + z), 0.0f);
        y = ny; z = nz;
        asm volatile("st.shared.f32 [%0], %1;" :: "r"(wb + 4u * (unsigned)r), "f"(y));
        xk[r] = y; xk[64 + r] = z;
        xk += 128;
        __syncthreads();
    }
}

// ---------------------------------------------------------------------------
// Primal: block per row (256 thr, 8 warps). Double-buffered 32-k z tiles in
// shared (coalesced float4 loads); Hinv rows register-resident; lane = n.
// p[b,k,n] = Hinv[n,:] . z[b,k,:] - Hinv[n,:] . b[b,:]
// ---------------------------------------------------------------------------
__global__ void __launch_bounds__(256) primal_kernel(
    const float* __restrict__ b, float* __restrict__ out)
{
    __shared__ __align__(16) float sZ[2][32 * 64];   // 16 KB
    int t = threadIdx.x, lane = t & 31, w = t >> 5;
    int row = blockIdx.x;

    ull hv[32];
    const ull* g2 = (const ull*)gHinv;
#pragma unroll
    for (int i = 0; i < 32; i++) hv[i] = g2[lane * 32 + i];

    const ull* b2 = (const ull*)(b + (size_t)row * MDIM);
    ull h0 = 0ull, h1 = 0ull;
#pragma unroll
    for (int i = 0; i < 16; i++) {
        FMA2(h0, hv[2 * i], b2[2 * i]);
        FMA2(h1, hv[2 * i + 1], b2[2 * i + 1]);
    }
    float hb = pairsum2(h0, h1);

    const float4* src = (const float4*)(out + (size_t)row * (ITERS + 1) * 128);
    float* Pp = out + (size_t)BSZ * (ITERS + 1) * 128 + (size_t)row * (ITERS + 1) * 32;

    // chunk ci (0..511) of a tile: k = tb + (ci>>4), float4 idx = k*32 + 16 + (ci&15)
    int k0a = (t >> 4), c0a = (t & 15);
    int k0b = ((t + 256) >> 4), c0b = ((t + 256) & 15);

    float4 p0, p1;
    if (k0a < ITERS + 1) p0 = src[(size_t)k0a * 32 + 16 + c0a];
    if (k0b < ITERS + 1) p1 = src[(size_t)k0b * 32 + 16 + c0b];
    ((float4*)sZ[0])[t] = p0;
    ((float4*)sZ[0])[t + 256] = p1;
    __syncthreads();

    int tt = 0;
    for (int tb = 0; tb < ITERS + 1; tb += 32, tt ^= 1) {
        int nb = tb + 32;
        bool more = nb < ITERS + 1;
        float4 n0, n1;
        if (more) {
            int ka = nb + k0a, kb = nb + k0b;
            if (ka < ITERS + 1) n0 = src[(size_t)ka * 32 + 16 + c0a];
            if (kb < ITERS + 1) n1 = src[(size_t)kb * 32 + 16 + c0b];
        }
#pragma unroll
        for (int i = 0; i < 4; i++) {
            int k = tb + w * 4 + i;
            if (k < ITERS + 1) {
                const ull* zz = (const ull*)(sZ[tt] + (w * 4 + i) * 64);
                ull s0 = 0ull, s1 = 0ull;
#pragma unroll
                for (int j = 0; j < 16; j++) {
                    FMA2(s0, hv[2 * j], zz[2 * j]);
                    FMA2(s1, hv[2 * j + 1], zz[2 * j + 1]);
                }
                Pp[(size_t)k * 32 + lane] = pairsum2(s0, s1) - hb;
            }
        }
        if (more) {
            ((float4*)sZ[tt ^ 1])[t] = n0;
            ((float4*)sZ[tt ^ 1])[t + 256] = n1;
        }
        __syncthreads();
    }
}

extern "C" void kernel_launch(void* const* d_in, const int* in_sizes, int n_in,
                              void* d_out, int out_size) {
    const float *q = nullptr, *b = nullptr, *P = nullptr, *H = nullptr;
    for (int i = 0; i < n_in; i++) {
        switch (in_sizes[i]) {
            case BSZ * NDIM:  q = (const float*)d_in[i]; break;  // 16384
            case BSZ * MDIM:  b = (const float*)d_in[i]; break;  // 32768
            case NDIM * NDIM: P = (const float*)d_in[i]; break;  // 1024
            case MDIM * NDIM: H = (const float*)d_in[i]; break;  // 2048
            default: break;                                      // iters ignored
        }
    }
    setup_kernel<<<1, 256>>>(P, H);
    solve_kernel<<<BSZ, 64>>>(q, b, (float*)d_out);
    primal_kernel<<<BSZ, 256>>>(b, (float*)d_out);
}